// round 1
// baseline (speedup 1.0000x reference)
#include <cuda_runtime.h>
#include <math.h>

#define BSZ   2048
#define INDIM 2047
#define HID   2048
#define OUTD  2048
#define G4    8192          // 4*HID
#define MAXP  100
#define NTHR  256

// ---------------- device scratch (no allocations allowed) ----------------
__device__ float g_base[(size_t)BSZ * G4];    // x@W_ih[:, :INDIM].T + b_ih + b_hh
__device__ float g_gates[(size_t)BSZ * G4];
__device__ float g_hx[(size_t)BSZ * HID];
__device__ float g_cx[(size_t)BSZ * HID];
__device__ float g_gxacc[BSZ];
__device__ float g_p[BSZ];
__device__ int   g_halted[BSZ];
__device__ int   g_num_halted;
__device__ int   g_done_step;   // steps t > g_done_step are skipped
__device__ int   g_ponder;

__device__ __forceinline__ float sigf(float x) { return 1.0f / (1.0f + expf(-x)); }

// ---------------- 128x128x8 SIMT SGEMM tile: C = A(MxK) @ B(NxK)^T ----------------
__device__ __forceinline__ void sgemm128(
    const float* __restrict__ A, int lda,
    const float* __restrict__ Bw, int ldb,
    int K, int m0, int n0,
    float (&acc)[8][8], float (*As)[128], float (*Bs)[128])
{
    const int tid = threadIdx.x;
    const int tx = tid & 15, ty = tid >> 4;
    for (int k0 = 0; k0 < K; k0 += 8) {
        #pragma unroll
        for (int u = 0; u < 4; u++) {
            int l   = tid * 4 + u;       // 0..1023
            int row = l >> 3;            // 0..127
            int kc  = l & 7;
            int kk  = k0 + kc;
            float av = 0.f, bv = 0.f;
            if (kk < K) {
                av = A[(size_t)(m0 + row) * lda + kk];
                bv = Bw[(size_t)(n0 + row) * ldb + kk];
            }
            As[kc][row] = av;
            Bs[kc][row] = bv;
        }
        __syncthreads();
        #pragma unroll
        for (int kk = 0; kk < 8; kk++) {
            float a[8], b[8];
            #pragma unroll
            for (int i = 0; i < 8; i++) a[i] = As[kk][ty * 8 + i];
            #pragma unroll
            for (int j = 0; j < 8; j++) b[j] = Bs[kk][tx * 8 + j];
            #pragma unroll
            for (int i = 0; i < 8; i++)
                #pragma unroll
                for (int j = 0; j < 8; j++)
                    acc[i][j] = fmaf(a[i], b[j], acc[i][j]);
        }
        __syncthreads();
    }
}

// ---------------- init ----------------
__global__ void __launch_bounds__(NTHR)
k_init(const float* __restrict__ hx0, const float* __restrict__ cx0,
       float* __restrict__ out)
{
    size_t i      = (size_t)blockIdx.x * blockDim.x + threadIdx.x;
    size_t stride = (size_t)gridDim.x * blockDim.x;
    for (size_t k = i; k < (size_t)3 * BSZ * HID; k += stride) out[k] = 0.f;
    for (size_t k = i; k < (size_t)BSZ * HID; k += stride) {
        g_hx[k] = hx0[k];
        g_cx[k] = cx0[k];
    }
    for (size_t k = i; k < BSZ; k += stride) {
        g_gxacc[k]  = 0.f;
        g_p[k]      = 0.f;
        g_halted[k] = 0;
    }
    if (i == 0) {
        g_num_halted = 0;
        g_done_step  = (1 << 30);
        g_ponder     = MAXP;
    }
}

// ---------------- base = x @ W_ih[:, :INDIM].T + b_ih + b_hh ----------------
__global__ void __launch_bounds__(NTHR)
k_base(const float* __restrict__ x, const float* __restrict__ W_ih,
       const float* __restrict__ b_ih, const float* __restrict__ b_hh)
{
    __shared__ float As[8][128], Bs[8][128];
    float acc[8][8] = {};
    int m0 = blockIdx.y * 128, n0 = blockIdx.x * 128;
    sgemm128(x, INDIM, W_ih, INDIM + 1, INDIM, m0, n0, acc, As, Bs);
    int tx = threadIdx.x & 15, ty = threadIdx.x >> 4;
    #pragma unroll
    for (int i = 0; i < 8; i++) {
        int m = m0 + ty * 8 + i;
        #pragma unroll
        for (int j = 0; j < 8; j++) {
            int n = n0 + tx * 8 + j;
            g_base[(size_t)m * G4 + n] = acc[i][j] + b_ih[n] + b_hh[n];
        }
    }
}

// ---------------- gates = base + hx @ W_hh.T (+ flag col on t==0) ----------------
__global__ void __launch_bounds__(NTHR)
k_gates(const float* __restrict__ W_hh, const float* __restrict__ W_ih, int t)
{
    if (t > g_done_step) return;
    int m0 = blockIdx.y * 128, n0 = blockIdx.x * 128;
    __shared__ int s_active;
    if (threadIdx.x == 0) s_active = 0;
    __syncthreads();
    if (threadIdx.x < 128 && !g_halted[m0 + threadIdx.x]) atomicOr(&s_active, 1);
    __syncthreads();
    if (!s_active) return;   // whole tile of halted rows -> skip

    __shared__ float As[8][128], Bs[8][128];
    float acc[8][8] = {};
    sgemm128(g_hx, HID, W_hh, HID, HID, m0, n0, acc, As, Bs);
    int tx = threadIdx.x & 15, ty = threadIdx.x >> 4;
    #pragma unroll
    for (int i = 0; i < 8; i++) {
        int m = m0 + ty * 8 + i;
        #pragma unroll
        for (int j = 0; j < 8; j++) {
            int n = n0 + tx * 8 + j;
            float v = acc[i][j] + g_base[(size_t)m * G4 + n];
            if (t == 0) v += W_ih[(size_t)n * (INDIM + 1) + INDIM];  // flag column
            g_gates[(size_t)m * G4 + n] = v;
        }
    }
}

// ---------------- LSTM elementwise ----------------
__global__ void __launch_bounds__(NTHR)
k_cell(int t)
{
    if (t > g_done_step) return;
    int idx = blockIdx.x * blockDim.x + threadIdx.x;
    int b = idx >> 11;            // / 2048
    if (g_halted[b]) return;
    int h = idx & 2047;
    size_t gb = (size_t)b * G4;
    float gi = g_gates[gb + h];
    float gf = g_gates[gb + HID + h];
    float gg = g_gates[gb + 2 * HID + h];
    float go = g_gates[gb + 3 * HID + h];
    float c  = sigf(gf) * g_cx[idx] + sigf(gi) * tanhf(gg);
    float hh = sigf(go) * tanhf(c);
    g_cx[idx] = c;
    g_hx[idx] = hh;
}

// ---------------- per-row: gx, ACT bookkeeping, ahx/acx accumulation ----------------
__global__ void __launch_bounds__(NTHR)
k_row(const float* __restrict__ W_p, const float* __restrict__ b_p,
      float* __restrict__ out, int t)
{
    if (t > g_done_step) return;
    int b = blockIdx.x;
    if (g_halted[b]) {
        if (threadIdx.x == 0) g_p[b] = 0.f;   // p must be 0 after halting
        return;
    }
    const float* hx = g_hx + (size_t)b * HID;
    const float* cx = g_cx + (size_t)b * HID;

    float s = 0.f;
    for (int h = threadIdx.x; h < HID; h += NTHR) s += hx[h] * W_p[h];
    #pragma unroll
    for (int o = 16; o; o >>= 1) s += __shfl_down_sync(0xffffffffu, s, o);
    __shared__ float red[8];
    if ((threadIdx.x & 31) == 0) red[threadIdx.x >> 5] = s;
    __syncthreads();

    __shared__ float s_p;
    if (threadIdx.x == 0) {
        float tot = 0.f;
        #pragma unroll
        for (int w = 0; w < 8; w++) tot += red[w];
        float gx   = sigf(tot + b_p[0]);
        float accn = g_gxacc[b] + gx;            // halt_prev == 0 here
        bool  halt = accn > 0.99f;               // 1.0 - EPS
        float rx   = halt ? (accn - 1.0f) : 0.f;
        float p    = gx - rx;
        accn      -= rx;
        g_gxacc[b] = accn;
        g_p[b]     = p;
        s_p        = p;
        if (halt) {
            g_halted[b] = 1;
            atomicAdd(&g_num_halted, 1);
        }
    }
    __syncthreads();
    float p = s_p;
    float* ahx = out;
    float* acx = out + (size_t)BSZ * HID;
    for (int h = threadIdx.x; h < HID; h += NTHR) {
        ahx[(size_t)b * HID + h] += p * hx[h];
        acx[(size_t)b * HID + h] += p * cx[h];
    }
}

// ---------------- aout += p * (hx @ W_o.T + b_o) ----------------
__global__ void __launch_bounds__(NTHR)
k_aout(const float* __restrict__ W_o, const float* __restrict__ b_o,
       float* __restrict__ out, int t)
{
    if (t > g_done_step) return;
    int m0 = blockIdx.y * 128, n0 = blockIdx.x * 128;
    __shared__ int s_active;
    if (threadIdx.x == 0) s_active = 0;
    __syncthreads();
    if (threadIdx.x < 128 && g_p[m0 + threadIdx.x] != 0.f) atomicOr(&s_active, 1);
    __syncthreads();
    if (!s_active) return;   // all weights zero for this tile

    __shared__ float As[8][128], Bs[8][128];
    float acc[8][8] = {};
    sgemm128(g_hx, HID, W_o, HID, HID, m0, n0, acc, As, Bs);
    float* aout = out + (size_t)2 * BSZ * HID;
    int tx = threadIdx.x & 15, ty = threadIdx.x >> 4;
    #pragma unroll
    for (int i = 0; i < 8; i++) {
        int m = m0 + ty * 8 + i;
        float p = g_p[m];
        if (p == 0.f) continue;
        #pragma unroll
        for (int j = 0; j < 8; j++) {
            int n = n0 + tx * 8 + j;
            aout[(size_t)m * OUTD + n] += p * (acc[i][j] + b_o[n]);
        }
    }
}

// ---------------- per-step all-halted check ----------------
__global__ void k_check(int t)
{
    if (t > g_done_step) return;
    if (g_num_halted >= BSZ) {
        g_done_step = t;        // steps > t will early-out
        g_ponder    = t + 1;
    }
}

// ---------------- finalize: write ponder_count ----------------
__global__ void k_fin(float* __restrict__ out, int out_size)
{
    if (blockIdx.x == 0 && threadIdx.x == 0)
        out[out_size - 1] = (float)g_ponder;
}

// ---------------- host ----------------
extern "C" void kernel_launch(void* const* d_in, const int* in_sizes, int n_in,
                              void* d_out, int out_size)
{
    const float* x    = (const float*)d_in[0];
    const float* hx0  = (const float*)d_in[1];
    const float* cx0  = (const float*)d_in[2];
    const float* W_ih = (const float*)d_in[3];
    const float* b_ih = (const float*)d_in[4];
    const float* W_hh = (const float*)d_in[5];
    const float* b_hh = (const float*)d_in[6];
    const float* W_p  = (const float*)d_in[7];
    const float* b_p  = (const float*)d_in[8];
    const float* W_o  = (const float*)d_in[9];
    const float* b_o  = (const float*)d_in[10];
    float* out = (float*)d_out;

    k_init<<<4096, NTHR>>>(hx0, cx0, out);

    dim3 gbig(G4 / 128, BSZ / 128);     // 64 x 16
    dim3 gout(OUTD / 128, BSZ / 128);   // 16 x 16
    k_base<<<gbig, NTHR>>>(x, W_ih, b_ih, b_hh);

    for (int t = 0; t < MAXP; t++) {
        k_gates<<<gbig, NTHR>>>(W_hh, W_ih, t);
        k_cell<<<(BSZ * HID) / NTHR, NTHR>>>(t);
        k_row<<<BSZ, NTHR>>>(W_p, b_p, out, t);
        k_aout<<<gout, NTHR>>>(W_o, b_o, out, t);
        k_check<<<1, 1>>>(t);
    }
    k_fin<<<1, 1>>>(out, out_size);
}

// round 3
// speedup vs baseline: 2.1627x; 2.1627x over previous
#include <cuda_runtime.h>
#include <math.h>

#define BSZ   2048
#define HID   2048
#define G4    8192          // 4*HID
#define OUTD  2048
#define INDIM 2047
#define KDIM  2048          // padded K for all GEMMs
#define MAXP  100
#define NTHR  256

// ---------------- device scratch (16B-aligned: float4 access!) ----------------
__device__ __align__(16) float g_xpad [(size_t)BSZ * KDIM];
__device__ __align__(16) float g_base [(size_t)BSZ * G4];
__device__ __align__(16) float g_gates[(size_t)BSZ * G4];
__device__ __align__(16) float g_hx   [(size_t)BSZ * HID];
__device__ __align__(16) float g_cx   [(size_t)BSZ * HID];
__device__ float g_gxacc[BSZ];
__device__ int   g_halted[BSZ];
__device__ int   g_num_halted;
__device__ int   g_done_step;
__device__ int   g_ponder;
__device__ int   g_blkdone[MAXP];

__device__ __forceinline__ float sigf(float x) { return 1.0f / (1.0f + expf(-x)); }

// ---------------- 128x128 tile SGEMM core: C += A(MxK)@B(NxK)^T ----------------
// K = KDIM (2048), lda = ldb = KDIM, double-buffered, BK=16, float4 loads.
__device__ __forceinline__ void gemm_tile(
    const float* __restrict__ A, const float* __restrict__ B,
    int m0, int n0, float (&acc)[8][8])
{
    __shared__ __align__(16) float As[2][16][128];
    __shared__ __align__(16) float Bs[2][16][128];
    const int tid = threadIdx.x;
    const int tx = tid & 15, ty = tid >> 4;

    float4 ra[2], rb[2];

    // prologue: load k0 = 0
    #pragma unroll
    for (int u = 0; u < 2; u++) {
        int idx = tid * 2 + u;
        int row = idx >> 2, c4 = idx & 3;
        ra[u] = *(const float4*)(A + (size_t)(m0 + row) * KDIM + c4 * 4);
        rb[u] = *(const float4*)(B + (size_t)(n0 + row) * KDIM + c4 * 4);
    }
    #pragma unroll
    for (int u = 0; u < 2; u++) {
        int idx = tid * 2 + u;
        int row = idx >> 2, c4 = idx & 3;
        As[0][c4*4+0][row] = ra[u].x; As[0][c4*4+1][row] = ra[u].y;
        As[0][c4*4+2][row] = ra[u].z; As[0][c4*4+3][row] = ra[u].w;
        Bs[0][c4*4+0][row] = rb[u].x; Bs[0][c4*4+1][row] = rb[u].y;
        Bs[0][c4*4+2][row] = rb[u].z; Bs[0][c4*4+3][row] = rb[u].w;
    }
    __syncthreads();

    for (int k0 = 0; k0 < KDIM; k0 += 16) {
        const int buf = (k0 >> 4) & 1;
        const bool more = (k0 + 16) < KDIM;
        if (more) {
            #pragma unroll
            for (int u = 0; u < 2; u++) {
                int idx = tid * 2 + u;
                int row = idx >> 2, c4 = idx & 3;
                ra[u] = *(const float4*)(A + (size_t)(m0 + row) * KDIM + k0 + 16 + c4 * 4);
                rb[u] = *(const float4*)(B + (size_t)(n0 + row) * KDIM + k0 + 16 + c4 * 4);
            }
        }
        #pragma unroll
        for (int kk = 0; kk < 16; kk++) {
            float4 a0 = *(const float4*)&As[buf][kk][ty * 8];
            float4 a1 = *(const float4*)&As[buf][kk][ty * 8 + 4];
            float4 b0 = *(const float4*)&Bs[buf][kk][tx * 8];
            float4 b1 = *(const float4*)&Bs[buf][kk][tx * 8 + 4];
            float a[8] = {a0.x,a0.y,a0.z,a0.w,a1.x,a1.y,a1.z,a1.w};
            float b[8] = {b0.x,b0.y,b0.z,b0.w,b1.x,b1.y,b1.z,b1.w};
            #pragma unroll
            for (int i = 0; i < 8; i++)
                #pragma unroll
                for (int j = 0; j < 8; j++)
                    acc[i][j] = fmaf(a[i], b[j], acc[i][j]);
        }
        if (more) {
            const int nb = buf ^ 1;
            #pragma unroll
            for (int u = 0; u < 2; u++) {
                int idx = tid * 2 + u;
                int row = idx >> 2, c4 = idx & 3;
                As[nb][c4*4+0][row] = ra[u].x; As[nb][c4*4+1][row] = ra[u].y;
                As[nb][c4*4+2][row] = ra[u].z; As[nb][c4*4+3][row] = ra[u].w;
                Bs[nb][c4*4+0][row] = rb[u].x; Bs[nb][c4*4+1][row] = rb[u].y;
                Bs[nb][c4*4+2][row] = rb[u].z; Bs[nb][c4*4+3][row] = rb[u].w;
            }
        }
        __syncthreads();
    }
}

// ---------------- init ----------------
__global__ void __launch_bounds__(NTHR)
k_init(const float* __restrict__ hx0, const float* __restrict__ cx0,
       float* __restrict__ out)
{
    size_t i      = (size_t)blockIdx.x * blockDim.x + threadIdx.x;
    size_t stride = (size_t)gridDim.x * blockDim.x;
    for (size_t k = i; k < (size_t)2 * BSZ * HID; k += stride) out[k] = 0.f;
    for (size_t k = i; k < (size_t)BSZ * HID; k += stride) {
        g_hx[k] = hx0[k];
        g_cx[k] = cx0[k];
    }
    for (size_t k = i; k < BSZ; k += stride) {
        g_gxacc[k]  = 0.f;
        g_halted[k] = 0;
    }
    for (size_t k = i; k < MAXP; k += stride) g_blkdone[k] = 0;
    if (i == 0) {
        g_num_halted = 0;
        g_done_step  = (1 << 30);
        g_ponder     = MAXP;
    }
}

// ---------------- pack x into padded buffer (zero flag column) ----------------
__global__ void __launch_bounds__(NTHR)
k_pack(const float* __restrict__ x)
{
    size_t i      = (size_t)blockIdx.x * blockDim.x + threadIdx.x;
    size_t stride = (size_t)gridDim.x * blockDim.x;
    for (size_t k = i; k < (size_t)BSZ * KDIM; k += stride) {
        size_t row = k >> 11;       // / 2048
        size_t col = k & 2047;
        g_xpad[k] = (col < INDIM) ? x[row * INDIM + col] : 0.f;
    }
}

// ---------------- base = xpad @ W_ih.T + b_ih + b_hh ----------------
__global__ void __launch_bounds__(NTHR)
k_base(const float* __restrict__ W_ih,
       const float* __restrict__ b_ih, const float* __restrict__ b_hh)
{
    float acc[8][8] = {};
    int m0 = blockIdx.y * 128, n0 = blockIdx.x * 128;
    gemm_tile(g_xpad, W_ih, m0, n0, acc);
    int tx = threadIdx.x & 15, ty = threadIdx.x >> 4;
    #pragma unroll
    for (int i = 0; i < 8; i++) {
        int m = m0 + ty * 8 + i;
        #pragma unroll
        for (int j = 0; j < 8; j++) {
            int n = n0 + tx * 8 + j;
            g_base[(size_t)m * G4 + n] = acc[i][j] + b_ih[n] + b_hh[n];
        }
    }
}

// ---------------- gates = base + hx @ W_hh.T (+ flag col at t==0) ----------------
__global__ void __launch_bounds__(NTHR)
k_gates(const float* __restrict__ W_hh, const float* __restrict__ W_ih, int t)
{
    if (t > g_done_step) return;
    int m0 = blockIdx.y * 128, n0 = blockIdx.x * 128;
    __shared__ int s_active;
    if (threadIdx.x == 0) s_active = 0;
    __syncthreads();
    if (threadIdx.x < 128 && !g_halted[m0 + threadIdx.x]) atomicOr(&s_active, 1);
    __syncthreads();
    if (!s_active) return;

    float acc[8][8] = {};
    gemm_tile(g_hx, W_hh, m0, n0, acc);
    int tx = threadIdx.x & 15, ty = threadIdx.x >> 4;
    #pragma unroll
    for (int i = 0; i < 8; i++) {
        int m = m0 + ty * 8 + i;
        #pragma unroll
        for (int j = 0; j < 8; j++) {
            int n = n0 + tx * 8 + j;
            float v = acc[i][j] + g_base[(size_t)m * G4 + n];
            if (t == 0) v += W_ih[(size_t)n * KDIM + INDIM];   // flag column
            g_gates[(size_t)m * G4 + n] = v;
        }
    }
}

// ---------------- fused: LSTM cell + ponder gate + ahx/acx accumulation ----------------
__global__ void __launch_bounds__(NTHR)
k_cellrow(const float* __restrict__ W_p, const float* __restrict__ b_p,
          float* __restrict__ out, int t)
{
    if (t > g_done_step) return;
    const int b = blockIdx.x;
    const bool active = !g_halted[b];
    __shared__ float red[8];
    __shared__ float s_p;

    if (active) {
        const size_t gb = (size_t)b * G4;
        const size_t hb = (size_t)b * HID;
        const int h0 = threadIdx.x * 8;

        float gi[8], gf[8], gg[8], go[8], cc[8], wp[8];
        *(float4*)&gi[0] = *(const float4*)(g_gates + gb + h0);
        *(float4*)&gi[4] = *(const float4*)(g_gates + gb + h0 + 4);
        *(float4*)&gf[0] = *(const float4*)(g_gates + gb + HID + h0);
        *(float4*)&gf[4] = *(const float4*)(g_gates + gb + HID + h0 + 4);
        *(float4*)&gg[0] = *(const float4*)(g_gates + gb + 2*HID + h0);
        *(float4*)&gg[4] = *(const float4*)(g_gates + gb + 2*HID + h0 + 4);
        *(float4*)&go[0] = *(const float4*)(g_gates + gb + 3*HID + h0);
        *(float4*)&go[4] = *(const float4*)(g_gates + gb + 3*HID + h0 + 4);
        *(float4*)&cc[0] = *(const float4*)(g_cx + hb + h0);
        *(float4*)&cc[4] = *(const float4*)(g_cx + hb + h0 + 4);
        *(float4*)&wp[0] = *(const float4*)(W_p + h0);
        *(float4*)&wp[4] = *(const float4*)(W_p + h0 + 4);

        float hv[8], cv[8];
        float s = 0.f;
        #pragma unroll
        for (int k = 0; k < 8; k++) {
            float c  = sigf(gf[k]) * cc[k] + sigf(gi[k]) * tanhf(gg[k]);
            float hh = sigf(go[k]) * tanhf(c);
            cv[k] = c; hv[k] = hh;
            s += hh * wp[k];
        }
        *(float4*)(g_cx + hb + h0)     = *(float4*)&cv[0];
        *(float4*)(g_cx + hb + h0 + 4) = *(float4*)&cv[4];
        *(float4*)(g_hx + hb + h0)     = *(float4*)&hv[0];
        *(float4*)(g_hx + hb + h0 + 4) = *(float4*)&hv[4];

        #pragma unroll
        for (int o = 16; o; o >>= 1) s += __shfl_down_sync(0xffffffffu, s, o);
        if ((threadIdx.x & 31) == 0) red[threadIdx.x >> 5] = s;
        __syncthreads();
        if (threadIdx.x == 0) {
            float tot = 0.f;
            #pragma unroll
            for (int w = 0; w < 8; w++) tot += red[w];
            float gx   = sigf(tot + b_p[0]);
            float accn = g_gxacc[b] + gx;
            bool  halt = accn > 0.99f;          // 1.0 - EPS
            float rx   = halt ? (accn - 1.0f) : 0.f;
            float p    = gx - rx;
            g_gxacc[b] = accn - rx;
            s_p        = p;
            if (halt) {
                g_halted[b] = 1;
                atomicAdd(&g_num_halted, 1);
            }
        }
        __syncthreads();
        const float p = s_p;
        float* ahx = out + hb;
        float* acx = out + (size_t)BSZ * HID + hb;
        float av[8], xv[8];
        *(float4*)&av[0] = *(const float4*)(ahx + h0);
        *(float4*)&av[4] = *(const float4*)(ahx + h0 + 4);
        *(float4*)&xv[0] = *(const float4*)(acx + h0);
        *(float4*)&xv[4] = *(const float4*)(acx + h0 + 4);
        #pragma unroll
        for (int k = 0; k < 8; k++) {
            av[k] += p * hv[k];
            xv[k] += p * cv[k];
        }
        *(float4*)(ahx + h0)     = *(float4*)&av[0];
        *(float4*)(ahx + h0 + 4) = *(float4*)&av[4];
        *(float4*)(acx + h0)     = *(float4*)&xv[0];
        *(float4*)(acx + h0 + 4) = *(float4*)&xv[4];
    }

    // all-halted detection: last block of this step checks the counter
    if (threadIdx.x == 0) {
        __threadfence();
        if (atomicAdd(&g_blkdone[t], 1) == BSZ - 1) {
            if (atomicAdd(&g_num_halted, 0) >= BSZ) {
                g_done_step = t;
                g_ponder    = t + 1;
            }
        }
    }
}

// ---------------- final: aout = ahx @ W_o.T + (sum p) * b_o ----------------
__global__ void __launch_bounds__(NTHR)
k_aout(const float* __restrict__ W_o, const float* __restrict__ b_o,
       float* __restrict__ out)
{
    float acc[8][8] = {};
    int m0 = blockIdx.y * 128, n0 = blockIdx.x * 128;
    const float* ahx = out;                       // [BSZ, HID]
    gemm_tile(ahx, W_o, m0, n0, acc);
    float* aout = out + (size_t)2 * BSZ * HID;
    int tx = threadIdx.x & 15, ty = threadIdx.x >> 4;
    #pragma unroll
    for (int i = 0; i < 8; i++) {
        int m = m0 + ty * 8 + i;
        float sp = g_gxacc[m];                    // = sum of ponder weights p
        #pragma unroll
        for (int j = 0; j < 8; j++) {
            int n = n0 + tx * 8 + j;
            aout[(size_t)m * OUTD + n] = acc[i][j] + sp * b_o[n];
        }
    }
}

// ---------------- finalize: ponder count ----------------
__global__ void k_fin(float* __restrict__ out, int out_size)
{
    if (blockIdx.x == 0 && threadIdx.x == 0)
        out[out_size - 1] = (float)g_ponder;
}

// ---------------- host ----------------
extern "C" void kernel_launch(void* const* d_in, const int* in_sizes, int n_in,
                              void* d_out, int out_size)
{
    const float* x    = (const float*)d_in[0];
    const float* hx0  = (const float*)d_in[1];
    const float* cx0  = (const float*)d_in[2];
    const float* W_ih = (const float*)d_in[3];
    const float* b_ih = (const float*)d_in[4];
    const float* W_hh = (const float*)d_in[5];
    const float* b_hh = (const float*)d_in[6];
    const float* W_p  = (const float*)d_in[7];
    const float* b_p  = (const float*)d_in[8];
    const float* W_o  = (const float*)d_in[9];
    const float* b_o  = (const float*)d_in[10];
    float* out = (float*)d_out;

    k_init<<<2048, NTHR>>>(hx0, cx0, out);
    k_pack<<<2048, NTHR>>>(x);

    dim3 gbig(G4 / 128, BSZ / 128);     // 64 x 16
    dim3 gout(OUTD / 128, BSZ / 128);   // 16 x 16
    k_base<<<gbig, NTHR>>>(W_ih, b_ih, b_hh);

    for (int t = 0; t < MAXP; t++) {
        k_gates<<<gbig, NTHR>>>(W_hh, W_ih, t);
        k_cellrow<<<BSZ, NTHR>>>(W_p, b_p, out, t);
    }
    k_aout<<<gout, NTHR>>>(W_o, b_o, out);
    k_fin<<<1, 1>>>(out, out_size);
}

// round 4
// speedup vs baseline: 2.3565x; 1.0896x over previous
#include <cuda_runtime.h>
#include <math.h>

#define BSZ   2048
#define HID   2048
#define G4    8192          // 4*HID
#define OUTD  2048
#define INDIM 2047
#define KDIM  2048
#define MAXP  100
#define NTHR  256

// ---------------- device scratch (16B-aligned for float4) ----------------
__device__ __align__(16) float g_xpad [(size_t)BSZ * KDIM];
__device__ __align__(16) float g_base [(size_t)BSZ * G4];
__device__ __align__(16) float g_gates[(size_t)BSZ * G4];   // compact slots
__device__ __align__(16) float g_hx   [(size_t)BSZ * HID];
__device__ __align__(16) float g_cx   [(size_t)BSZ * HID];
__device__ float g_gxacc[BSZ];
__device__ int   g_halted[BSZ];
__device__ int   g_rowidx[2][BSZ + 128];   // double-buffered active-row list
__device__ int   g_nactive;
__device__ int   g_done_step;
__device__ int   g_ponder;

__device__ __forceinline__ float sigf(float x) { return 1.0f / (1.0f + expf(-x)); }

// -------- 128x128 tile SGEMM: C += A(gathered MxK) @ B(NxK)^T --------
// A rows gathered via rows[] (or identity when rows==nullptr).
__device__ __forceinline__ void gemm_tile(
    const float* __restrict__ A, const int* __restrict__ rows,
    const float* __restrict__ B,
    int m0, int n0, float (&acc)[8][8])
{
    __shared__ __align__(16) float As[2][16][128];
    __shared__ __align__(16) float Bs[2][16][128];
    __shared__ int rowmap[128];
    const int tid = threadIdx.x;
    const int tx = tid & 15, ty = tid >> 4;

    if (rows) {
        if (tid < 128) rowmap[tid] = rows[m0 + tid];
        __syncthreads();
    }

    float4 ra[2], rb[2];
    #pragma unroll
    for (int u = 0; u < 2; u++) {
        int idx = tid * 2 + u;
        int row = idx >> 2, c4 = idx & 3;
        int arow = rows ? rowmap[row] : (m0 + row);
        ra[u] = *(const float4*)(A + (size_t)arow * KDIM + c4 * 4);
        rb[u] = *(const float4*)(B + (size_t)(n0 + row) * KDIM + c4 * 4);
    }
    #pragma unroll
    for (int u = 0; u < 2; u++) {
        int idx = tid * 2 + u;
        int row = idx >> 2, c4 = idx & 3;
        As[0][c4*4+0][row] = ra[u].x; As[0][c4*4+1][row] = ra[u].y;
        As[0][c4*4+2][row] = ra[u].z; As[0][c4*4+3][row] = ra[u].w;
        Bs[0][c4*4+0][row] = rb[u].x; Bs[0][c4*4+1][row] = rb[u].y;
        Bs[0][c4*4+2][row] = rb[u].z; Bs[0][c4*4+3][row] = rb[u].w;
    }
    __syncthreads();

    for (int k0 = 0; k0 < KDIM; k0 += 16) {
        const int buf = (k0 >> 4) & 1;
        const bool more = (k0 + 16) < KDIM;
        if (more) {
            #pragma unroll
            for (int u = 0; u < 2; u++) {
                int idx = tid * 2 + u;
                int row = idx >> 2, c4 = idx & 3;
                int arow = rows ? rowmap[row] : (m0 + row);
                ra[u] = *(const float4*)(A + (size_t)arow * KDIM + k0 + 16 + c4 * 4);
                rb[u] = *(const float4*)(B + (size_t)(n0 + row) * KDIM + k0 + 16 + c4 * 4);
            }
        }
        #pragma unroll
        for (int kk = 0; kk < 16; kk++) {
            float4 a0 = *(const float4*)&As[buf][kk][ty * 8];
            float4 a1 = *(const float4*)&As[buf][kk][ty * 8 + 4];
            float4 b0 = *(const float4*)&Bs[buf][kk][tx * 8];
            float4 b1 = *(const float4*)&Bs[buf][kk][tx * 8 + 4];
            float a[8] = {a0.x,a0.y,a0.z,a0.w,a1.x,a1.y,a1.z,a1.w};
            float b[8] = {b0.x,b0.y,b0.z,b0.w,b1.x,b1.y,b1.z,b1.w};
            #pragma unroll
            for (int i = 0; i < 8; i++)
                #pragma unroll
                for (int j = 0; j < 8; j++)
                    acc[i][j] = fmaf(a[i], b[j], acc[i][j]);
        }
        if (more) {
            const int nb = buf ^ 1;
            #pragma unroll
            for (int u = 0; u < 2; u++) {
                int idx = tid * 2 + u;
                int row = idx >> 2, c4 = idx & 3;
                As[nb][c4*4+0][row] = ra[u].x; As[nb][c4*4+1][row] = ra[u].y;
                As[nb][c4*4+2][row] = ra[u].z; As[nb][c4*4+3][row] = ra[u].w;
                Bs[nb][c4*4+0][row] = rb[u].x; Bs[nb][c4*4+1][row] = rb[u].y;
                Bs[nb][c4*4+2][row] = rb[u].z; Bs[nb][c4*4+3][row] = rb[u].w;
            }
        }
        __syncthreads();
    }
}

// ---------------- init ----------------
__global__ void __launch_bounds__(NTHR)
k_init(const float* __restrict__ hx0, const float* __restrict__ cx0,
       float* __restrict__ out)
{
    size_t i      = (size_t)blockIdx.x * blockDim.x + threadIdx.x;
    size_t stride = (size_t)gridDim.x * blockDim.x;
    for (size_t k = i; k < (size_t)2 * BSZ * HID; k += stride) out[k] = 0.f;
    for (size_t k = i; k < (size_t)BSZ * HID; k += stride) {
        g_hx[k] = hx0[k];
        g_cx[k] = cx0[k];
    }
    for (size_t k = i; k < BSZ + 128; k += stride) {
        if (k < BSZ) {
            g_gxacc[k]  = 0.f;
            g_halted[k] = 0;
            g_rowidx[0][k] = (int)k;
        } else {
            g_rowidx[0][k] = 0;
        }
    }
    if (i == 0) {
        g_nactive   = BSZ;
        g_done_step = (1 << 30);
        g_ponder    = MAXP;
    }
}

// ---------------- pack x into padded buffer ----------------
__global__ void __launch_bounds__(NTHR)
k_pack(const float* __restrict__ x)
{
    size_t i      = (size_t)blockIdx.x * blockDim.x + threadIdx.x;
    size_t stride = (size_t)gridDim.x * blockDim.x;
    for (size_t k = i; k < (size_t)BSZ * KDIM; k += stride) {
        size_t row = k >> 11;
        size_t col = k & 2047;
        g_xpad[k] = (col < INDIM) ? x[row * INDIM + col] : 0.f;
    }
}

// ---------------- base = xpad @ W_ih.T + b_ih + b_hh ----------------
__global__ void __launch_bounds__(NTHR)
k_base(const float* __restrict__ W_ih,
       const float* __restrict__ b_ih, const float* __restrict__ b_hh)
{
    float acc[8][8] = {};
    int m0 = blockIdx.y * 128, n0 = blockIdx.x * 128;
    gemm_tile(g_xpad, nullptr, W_ih, m0, n0, acc);
    int tx = threadIdx.x & 15, ty = threadIdx.x >> 4;
    #pragma unroll
    for (int i = 0; i < 8; i++) {
        int m = m0 + ty * 8 + i;
        #pragma unroll
        for (int j = 0; j < 8; j++) {
            int n = n0 + tx * 8 + j;
            g_base[(size_t)m * G4 + n] = acc[i][j] + b_ih[n] + b_hh[n];
        }
    }
}

// ---- gates[slot] = base[row] + hx[row] @ W_hh.T (+ flag col at t==0) ----
__global__ void __launch_bounds__(NTHR)
k_gates(const float* __restrict__ W_hh, const float* __restrict__ W_ih, int t)
{
    if (t > g_done_step) return;
    int m0 = blockIdx.y * 128;
    if (m0 >= g_nactive) return;
    int n0 = blockIdx.x * 128;
    const int* rows = g_rowidx[t & 1];

    float acc[8][8] = {};
    gemm_tile(g_hx, rows, W_hh, m0, n0, acc);
    int tx = threadIdx.x & 15, ty = threadIdx.x >> 4;
    #pragma unroll
    for (int i = 0; i < 8; i++) {
        int slot = m0 + ty * 8 + i;
        int row  = rows[slot];
        #pragma unroll
        for (int j = 0; j < 8; j++) {
            int n = n0 + tx * 8 + j;
            float v = acc[i][j] + g_base[(size_t)row * G4 + n];
            if (t == 0) v += W_ih[(size_t)n * KDIM + INDIM];
            g_gates[(size_t)slot * G4 + n] = v;
        }
    }
}

// ---- fused: LSTM cell + ponder gate + ahx/acx accumulation (per active slot) ----
__global__ void __launch_bounds__(NTHR)
k_cellrow(const float* __restrict__ W_p, const float* __restrict__ b_p,
          float* __restrict__ out, int t)
{
    if (t > g_done_step) return;
    const int slot = blockIdx.x;
    if (slot >= g_nactive) return;
    const int b = g_rowidx[t & 1][slot];

    __shared__ float red[8];
    __shared__ float s_p;

    const size_t gb = (size_t)slot * G4;
    const size_t hb = (size_t)b * HID;
    const int h0 = threadIdx.x * 8;

    float gi[8], gf[8], gg[8], go[8], cc[8], wp[8];
    *(float4*)&gi[0] = *(const float4*)(g_gates + gb + h0);
    *(float4*)&gi[4] = *(const float4*)(g_gates + gb + h0 + 4);
    *(float4*)&gf[0] = *(const float4*)(g_gates + gb + HID + h0);
    *(float4*)&gf[4] = *(const float4*)(g_gates + gb + HID + h0 + 4);
    *(float4*)&gg[0] = *(const float4*)(g_gates + gb + 2*HID + h0);
    *(float4*)&gg[4] = *(const float4*)(g_gates + gb + 2*HID + h0 + 4);
    *(float4*)&go[0] = *(const float4*)(g_gates + gb + 3*HID + h0);
    *(float4*)&go[4] = *(const float4*)(g_gates + gb + 3*HID + h0 + 4);
    *(float4*)&cc[0] = *(const float4*)(g_cx + hb + h0);
    *(float4*)&cc[4] = *(const float4*)(g_cx + hb + h0 + 4);
    *(float4*)&wp[0] = *(const float4*)(W_p + h0);
    *(float4*)&wp[4] = *(const float4*)(W_p + h0 + 4);

    float hv[8], cv[8];
    float s = 0.f;
    #pragma unroll
    for (int k = 0; k < 8; k++) {
        float c  = sigf(gf[k]) * cc[k] + sigf(gi[k]) * tanhf(gg[k]);
        float hh = sigf(go[k]) * tanhf(c);
        cv[k] = c; hv[k] = hh;
        s += hh * wp[k];
    }
    *(float4*)(g_cx + hb + h0)     = *(float4*)&cv[0];
    *(float4*)(g_cx + hb + h0 + 4) = *(float4*)&cv[4];
    *(float4*)(g_hx + hb + h0)     = *(float4*)&hv[0];
    *(float4*)(g_hx + hb + h0 + 4) = *(float4*)&hv[4];

    #pragma unroll
    for (int o = 16; o; o >>= 1) s += __shfl_down_sync(0xffffffffu, s, o);
    if ((threadIdx.x & 31) == 0) red[threadIdx.x >> 5] = s;
    __syncthreads();
    if (threadIdx.x == 0) {
        float tot = 0.f;
        #pragma unroll
        for (int w = 0; w < 8; w++) tot += red[w];
        float gx   = sigf(tot + b_p[0]);
        float accn = g_gxacc[b] + gx;
        bool  halt = accn > 0.99f;              // 1.0 - EPS
        float rx   = halt ? (accn - 1.0f) : 0.f;
        float p    = gx - rx;
        g_gxacc[b] = accn - rx;
        s_p        = p;
        if (halt) g_halted[b] = 1;
    }
    __syncthreads();
    const float p = s_p;
    float* ahx = out + hb;
    float* acx = out + (size_t)BSZ * HID + hb;
    float av[8], xv[8];
    *(float4*)&av[0] = *(const float4*)(ahx + h0);
    *(float4*)&av[4] = *(const float4*)(ahx + h0 + 4);
    *(float4*)&xv[0] = *(const float4*)(acx + h0);
    *(float4*)&xv[4] = *(const float4*)(acx + h0 + 4);
    #pragma unroll
    for (int k = 0; k < 8; k++) {
        av[k] += p * hv[k];
        xv[k] += p * cv[k];
    }
    *(float4*)(ahx + h0)     = *(float4*)&av[0];
    *(float4*)(ahx + h0 + 4) = *(float4*)&av[4];
    *(float4*)(acx + h0)     = *(float4*)&xv[0];
    *(float4*)(acx + h0 + 4) = *(float4*)&xv[4];
}

// ---- compaction: build next step's active-row list; detect all-halted ----
__global__ void __launch_bounds__(1024)
k_compact(int t)
{
    if (t > g_done_step) return;
    __shared__ int s_count;
    if (threadIdx.x == 0) s_count = 0;
    __syncthreads();

    const int n = g_nactive;
    const int* cur = g_rowidx[t & 1];
    int* nxt = g_rowidx[(t + 1) & 1];

    #pragma unroll
    for (int u = 0; u < 2; u++) {
        int slot = threadIdx.x + u * 1024;
        if (slot < n) {
            int row = cur[slot];
            if (!g_halted[row]) {
                int pos = atomicAdd(&s_count, 1);
                nxt[pos] = row;
            }
        }
    }
    __syncthreads();
    int cnt = s_count;
    // pad to next 128 multiple with row 0 (safe loads, never consumed)
    int pad_end = (cnt + 127) & ~127;
    for (int k = cnt + (int)threadIdx.x; k < pad_end; k += 1024) nxt[k] = 0;
    if (threadIdx.x == 0) {
        g_nactive = cnt;
        if (cnt == 0 && t < g_done_step) {
            g_done_step = t;        // steps > t skip everything
            g_ponder    = t + 1;
        }
    }
}

// ---------------- final: aout = ahx @ W_o.T + (sum p) * b_o ----------------
__global__ void __launch_bounds__(NTHR)
k_aout(const float* __restrict__ W_o, const float* __restrict__ b_o,
       float* __restrict__ out)
{
    float acc[8][8] = {};
    int m0 = blockIdx.y * 128, n0 = blockIdx.x * 128;
    const float* ahx = out;
    gemm_tile(ahx, nullptr, W_o, m0, n0, acc);
    float* aout = out + (size_t)2 * BSZ * HID;
    int tx = threadIdx.x & 15, ty = threadIdx.x >> 4;
    #pragma unroll
    for (int i = 0; i < 8; i++) {
        int m = m0 + ty * 8 + i;
        float sp = g_gxacc[m];
        #pragma unroll
        for (int j = 0; j < 8; j++) {
            int n = n0 + tx * 8 + j;
            aout[(size_t)m * OUTD + n] = acc[i][j] + sp * b_o[n];
        }
    }
}

// ---------------- finalize ----------------
__global__ void k_fin(float* __restrict__ out, int out_size)
{
    if (blockIdx.x == 0 && threadIdx.x == 0)
        out[out_size - 1] = (float)g_ponder;
}

// ---------------- host ----------------
extern "C" void kernel_launch(void* const* d_in, const int* in_sizes, int n_in,
                              void* d_out, int out_size)
{
    const float* x    = (const float*)d_in[0];
    const float* hx0  = (const float*)d_in[1];
    const float* cx0  = (const float*)d_in[2];
    const float* W_ih = (const float*)d_in[3];
    const float* b_ih = (const float*)d_in[4];
    const float* W_hh = (const float*)d_in[5];
    const float* b_hh = (const float*)d_in[6];
    const float* W_p  = (const float*)d_in[7];
    const float* b_p  = (const float*)d_in[8];
    const float* W_o  = (const float*)d_in[9];
    const float* b_o  = (const float*)d_in[10];
    float* out = (float*)d_out;

    k_init<<<2048, NTHR>>>(hx0, cx0, out);
    k_pack<<<2048, NTHR>>>(x);

    dim3 gbig(G4 / 128, BSZ / 128);     // 64 x 16
    dim3 gout(OUTD / 128, BSZ / 128);   // 16 x 16
    k_base<<<gbig, NTHR>>>(W_ih, b_ih, b_hh);

    for (int t = 0; t < MAXP; t++) {
        k_gates<<<gbig, NTHR>>>(W_hh, W_ih, t);
        k_cellrow<<<BSZ, NTHR>>>(W_p, b_p, out, t);
        k_compact<<<1, 1024>>>(t);
    }
    k_aout<<<gout, NTHR>>>(W_o, b_o, out);
    k_fin<<<1, 1>>>(out, out_size);
}

// round 7
// speedup vs baseline: 3.8835x; 1.6480x over previous
#include <cuda_runtime.h>
#include <cuda_bf16.h>
#include <math.h>

#define BSZ   2048
#define HID   2048
#define G4    8192
#define OUTD  2048
#define INDIM 2047
#define KDIM  2048
#define KB3   6144          // 3 * KDIM (bf16x3 K-extension)
#define MAXP  100
#define NTHR  256
#define LDA   40            // smem row stride (32 + 8 pad)

// ---------------- device scratch ----------------
__device__ __align__(16) __nv_bfloat16 g_xpadb[(size_t)BSZ * KB3];  // A-side (hi,hi,lo)
__device__ __align__(16) __nv_bfloat16 g_hxb  [(size_t)BSZ * KB3];  // A-side
__device__ __align__(16) __nv_bfloat16 g_ahxb [(size_t)BSZ * KB3];  // A-side
__device__ __align__(16) __nv_bfloat16 g_wihb [(size_t)G4  * KB3];  // B-side (hi,lo,hi)
__device__ __align__(16) __nv_bfloat16 g_whhb [(size_t)G4  * KB3];  // B-side
__device__ __align__(16) __nv_bfloat16 g_wob  [(size_t)OUTD* KB3];  // B-side
__device__ __align__(16) float g_base [(size_t)BSZ * G4];
__device__ __align__(16) float g_gates[(size_t)BSZ * G4];
__device__ __align__(16) float g_hx   [(size_t)BSZ * HID];
__device__ __align__(16) float g_cx   [(size_t)BSZ * HID];
__device__ float g_gxacc[BSZ];
__device__ int   g_halted[BSZ];
__device__ int   g_rowidx[2][BSZ + 128];
__device__ int   g_nactive;
__device__ int   g_done_step;
__device__ int   g_ponder;

__device__ __forceinline__ float sigf(float x) { return 1.0f / (1.0f + expf(-x)); }

__device__ __forceinline__ void split_bf16(float v, __nv_bfloat16& hi, __nv_bfloat16& lo)
{
    hi = __float2bfloat16(v);
    lo = __float2bfloat16(v - __bfloat162float(hi));
}

__device__ __forceinline__ void mma16816(float& d0, float& d1, float& d2, float& d3,
                                         unsigned a0, unsigned a1, unsigned a2, unsigned a3,
                                         unsigned b0, unsigned b1)
{
    asm volatile("mma.sync.aligned.m16n8k16.row.col.f32.bf16.bf16.f32 "
                 "{%0,%1,%2,%3}, {%4,%5,%6,%7}, {%8,%9}, {%0,%1,%2,%3};"
                 : "+f"(d0), "+f"(d1), "+f"(d2), "+f"(d3)
                 : "r"(a0), "r"(a1), "r"(a2), "r"(a3), "r"(b0), "r"(b1));
}

// ------------- 128x128 bf16 MMA GEMM tile: acc += A'(MxK') @ B'(NxK')^T -------------
// 256 threads = 8 warps in 2x4 grid; warp tile 64x32.
// Fragments loaded with plain LDS32 at the PTX fragment coordinates.
__device__ __forceinline__ void mma_gemm(
    const __nv_bfloat16* __restrict__ A, const int* __restrict__ rows,
    const __nv_bfloat16* __restrict__ B,
    int m0, int n0, float (&acc)[4][4][4], int* rowmap)
{
    __shared__ __align__(16) __nv_bfloat16 As[128 * LDA];
    __shared__ __align__(16) __nv_bfloat16 Bs[128 * LDA];
    const int tid = threadIdx.x;

    if (rows) {
        if (tid < 128) rowmap[tid] = rows[m0 + tid];
        __syncthreads();
    }

    const int lrow = tid >> 1;
    const int lcol = (tid & 1) << 4;            // 0 or 16
    const int arow = rows ? rowmap[lrow] : (m0 + lrow);
    const __nv_bfloat16* ag = A + (size_t)arow * KB3 + lcol;
    const __nv_bfloat16* bg = B + (size_t)(n0 + lrow) * KB3 + lcol;
    const int soff = lrow * LDA + lcol;

    const int lane = tid & 31, warpid = tid >> 5;
    const int wm = warpid >> 2, wn = warpid & 3;
    const int g  = lane >> 2;                    // fragment group id (row/n)
    const int cp = (lane & 3) * 2;               // fragment k-pair base

    uint4 a0v = *(const uint4*)(ag);
    uint4 a1v = *(const uint4*)(ag + 8);
    uint4 b0v = *(const uint4*)(bg);
    uint4 b1v = *(const uint4*)(bg + 8);

    const int nk = KB3 / 32;
    for (int kc = 0; kc < nk; kc++) {
        *(uint4*)&As[soff]     = a0v;
        *(uint4*)&As[soff + 8] = a1v;
        *(uint4*)&Bs[soff]     = b0v;
        *(uint4*)&Bs[soff + 8] = b1v;
        __syncthreads();

        if (kc + 1 < nk) {
            const int ko = (kc + 1) * 32;
            a0v = *(const uint4*)(ag + ko);
            a1v = *(const uint4*)(ag + ko + 8);
            b0v = *(const uint4*)(bg + ko);
            b1v = *(const uint4*)(bg + ko + 8);
        }

        #pragma unroll
        for (int kh = 0; kh < 2; kh++) {
            const int kb = kh * 16 + cp;
            unsigned af[4][4], bfr[4][2];
            #pragma unroll
            for (int mi = 0; mi < 4; mi++) {
                int r = wm * 64 + mi * 16 + g;
                af[mi][0] = *(const unsigned*)&As[r * LDA + kb];
                af[mi][1] = *(const unsigned*)&As[(r + 8) * LDA + kb];
                af[mi][2] = *(const unsigned*)&As[r * LDA + kb + 8];
                af[mi][3] = *(const unsigned*)&As[(r + 8) * LDA + kb + 8];
            }
            #pragma unroll
            for (int ni = 0; ni < 4; ni++) {
                int r = wn * 32 + ni * 8 + g;
                bfr[ni][0] = *(const unsigned*)&Bs[r * LDA + kb];
                bfr[ni][1] = *(const unsigned*)&Bs[r * LDA + kb + 8];
            }
            #pragma unroll
            for (int mi = 0; mi < 4; mi++)
                #pragma unroll
                for (int ni = 0; ni < 4; ni++)
                    mma16816(acc[mi][ni][0], acc[mi][ni][1], acc[mi][ni][2], acc[mi][ni][3],
                             af[mi][0], af[mi][1], af[mi][2], af[mi][3],
                             bfr[ni][0], bfr[ni][1]);
        }
        __syncthreads();
    }
}

// ---------------- init ----------------
__global__ void __launch_bounds__(NTHR)
k_init(const float* __restrict__ hx0, const float* __restrict__ cx0,
       float* __restrict__ out)
{
    size_t i      = (size_t)blockIdx.x * blockDim.x + threadIdx.x;
    size_t stride = (size_t)gridDim.x * blockDim.x;
    for (size_t k = i; k < (size_t)2 * BSZ * HID; k += stride) out[k] = 0.f;
    for (size_t k = i; k < (size_t)BSZ * HID; k += stride) {
        float h = hx0[k], c = cx0[k];
        g_hx[k] = h;
        g_cx[k] = c;
        size_t row = k >> 11, col = k & 2047;
        __nv_bfloat16 hi, lo;
        split_bf16(h, hi, lo);
        g_hxb[row * KB3 + col]        = hi;
        g_hxb[row * KB3 + 2048 + col] = hi;
        g_hxb[row * KB3 + 4096 + col] = lo;
    }
    for (size_t k = i; k < BSZ + 128; k += stride) {
        if (k < BSZ) {
            g_gxacc[k]  = 0.f;
            g_halted[k] = 0;
            g_rowidx[0][k] = (int)k;
        } else {
            g_rowidx[0][k] = 0;
        }
    }
    if (i == 0) {
        g_nactive   = BSZ;
        g_done_step = (1 << 30);
        g_ponder    = MAXP;
    }
}

// ---------------- pack x into bf16x3 A-layout ----------------
__global__ void __launch_bounds__(NTHR)
k_pack(const float* __restrict__ x)
{
    size_t i      = (size_t)blockIdx.x * blockDim.x + threadIdx.x;
    size_t stride = (size_t)gridDim.x * blockDim.x;
    for (size_t k = i; k < (size_t)BSZ * KDIM; k += stride) {
        size_t row = k >> 11, col = k & 2047;
        float v = (col < INDIM) ? x[row * INDIM + col] : 0.f;
        __nv_bfloat16 hi, lo;
        split_bf16(v, hi, lo);
        g_xpadb[row * KB3 + col]        = hi;
        g_xpadb[row * KB3 + 2048 + col] = hi;
        g_xpadb[row * KB3 + 4096 + col] = lo;
    }
}

// -------- weight conversion to bf16x3 B-layout (hi,lo,hi) --------
// NOTE: destination selected by tag INSIDE device code. Passing a __device__
// array symbol as a kernel argument from host code silently yields the host
// shadow address (ATS-coherent on GB300 -> silent wrong writes). Never again.
__global__ void __launch_bounds__(NTHR)
k_cvtw(const float* __restrict__ W, int which, int nrows)
{
    __nv_bfloat16* Wb = (which == 0) ? g_wihb : (which == 1) ? g_whhb : g_wob;
    size_t total  = (size_t)nrows * KDIM;
    size_t i      = (size_t)blockIdx.x * blockDim.x + threadIdx.x;
    size_t stride = (size_t)gridDim.x * blockDim.x;
    for (size_t k = i; k < total; k += stride) {
        size_t row = k >> 11, col = k & 2047;
        __nv_bfloat16 hi, lo;
        split_bf16(W[k], hi, lo);
        Wb[row * KB3 + col]        = hi;
        Wb[row * KB3 + 2048 + col] = lo;
        Wb[row * KB3 + 4096 + col] = hi;
    }
}

// ---------------- ahx -> bf16x3 A-layout ----------------
__global__ void __launch_bounds__(NTHR)
k_cvt_ahx(const float* __restrict__ out)
{
    size_t i      = (size_t)blockIdx.x * blockDim.x + threadIdx.x;
    size_t stride = (size_t)gridDim.x * blockDim.x;
    for (size_t k = i; k < (size_t)BSZ * HID; k += stride) {
        size_t row = k >> 11, col = k & 2047;
        __nv_bfloat16 hi, lo;
        split_bf16(out[k], hi, lo);
        g_ahxb[row * KB3 + col]        = hi;
        g_ahxb[row * KB3 + 2048 + col] = hi;
        g_ahxb[row * KB3 + 4096 + col] = lo;
    }
}

// ---------------- base = xpad @ W_ih.T + b_ih + b_hh ----------------
__global__ void __launch_bounds__(NTHR)
k_base_mma(const float* __restrict__ b_ih, const float* __restrict__ b_hh)
{
    __shared__ int rowmap[128];
    float acc[4][4][4] = {};
    int m0 = blockIdx.y * 128, n0 = blockIdx.x * 128;
    mma_gemm(g_xpadb, nullptr, g_wihb, m0, n0, acc, rowmap);
    int lane = threadIdx.x & 31, warpid = threadIdx.x >> 5;
    int wm = warpid >> 2, wn = warpid & 3;
    #pragma unroll
    for (int mi = 0; mi < 4; mi++)
        #pragma unroll
        for (int e2 = 0; e2 < 2; e2++) {
            int m = m0 + wm * 64 + mi * 16 + (lane >> 2) + e2 * 8;
            #pragma unroll
            for (int ni = 0; ni < 4; ni++) {
                int n = n0 + wn * 32 + ni * 8 + (lane & 3) * 2;
                float2 w;
                w.x = acc[mi][ni][e2 * 2 + 0] + b_ih[n]     + b_hh[n];
                w.y = acc[mi][ni][e2 * 2 + 1] + b_ih[n + 1] + b_hh[n + 1];
                *(float2*)&g_base[(size_t)m * G4 + n] = w;
            }
        }
}

// ---- gates[slot] = base[row] + hx[row] @ W_hh.T (+ flag col at t==0) ----
__global__ void __launch_bounds__(NTHR)
k_gates_mma(const float* __restrict__ W_ih, int t)
{
    if (t > g_done_step) return;
    int m0 = blockIdx.y * 128;
    if (m0 >= g_nactive) return;
    int n0 = blockIdx.x * 128;
    __shared__ int rowmap[128];
    float acc[4][4][4] = {};
    mma_gemm(g_hxb, g_rowidx[t & 1], g_whhb, m0, n0, acc, rowmap);

    int lane = threadIdx.x & 31, warpid = threadIdx.x >> 5;
    int wm = warpid >> 2, wn = warpid & 3;
    #pragma unroll
    for (int mi = 0; mi < 4; mi++)
        #pragma unroll
        for (int e2 = 0; e2 < 2; e2++) {
            int ml   = wm * 64 + mi * 16 + (lane >> 2) + e2 * 8;
            int slot = m0 + ml;
            int row  = rowmap[ml];
            #pragma unroll
            for (int ni = 0; ni < 4; ni++) {
                int n = n0 + wn * 32 + ni * 8 + (lane & 3) * 2;
                float v0 = acc[mi][ni][e2 * 2 + 0] + g_base[(size_t)row * G4 + n];
                float v1 = acc[mi][ni][e2 * 2 + 1] + g_base[(size_t)row * G4 + n + 1];
                if (t == 0) {
                    v0 += W_ih[(size_t)n       * KDIM + INDIM];
                    v1 += W_ih[(size_t)(n + 1) * KDIM + INDIM];
                }
                float2 w; w.x = v0; w.y = v1;
                *(float2*)&g_gates[(size_t)slot * G4 + n] = w;
            }
        }
}

// ---- fused: LSTM cell + ponder + ahx/acx accumulation + hxb write ----
__global__ void __launch_bounds__(NTHR)
k_cellrow(const float* __restrict__ W_p, const float* __restrict__ b_p,
          float* __restrict__ out, int t)
{
    if (t > g_done_step) return;
    const int slot = blockIdx.x;
    if (slot >= g_nactive) return;
    const int b = g_rowidx[t & 1][slot];

    __shared__ float red[8];
    __shared__ float s_p;

    const size_t gb = (size_t)slot * G4;
    const size_t hb = (size_t)b * HID;
    const int h0 = threadIdx.x * 8;

    float gi[8], gf[8], gg[8], go[8], cc[8], wp[8];
    *(float4*)&gi[0] = *(const float4*)(g_gates + gb + h0);
    *(float4*)&gi[4] = *(const float4*)(g_gates + gb + h0 + 4);
    *(float4*)&gf[0] = *(const float4*)(g_gates + gb + HID + h0);
    *(float4*)&gf[4] = *(const float4*)(g_gates + gb + HID + h0 + 4);
    *(float4*)&gg[0] = *(const float4*)(g_gates + gb + 2*HID + h0);
    *(float4*)&gg[4] = *(const float4*)(g_gates + gb + 2*HID + h0 + 4);
    *(float4*)&go[0] = *(const float4*)(g_gates + gb + 3*HID + h0);
    *(float4*)&go[4] = *(const float4*)(g_gates + gb + 3*HID + h0 + 4);
    *(float4*)&cc[0] = *(const float4*)(g_cx + hb + h0);
    *(float4*)&cc[4] = *(const float4*)(g_cx + hb + h0 + 4);
    *(float4*)&wp[0] = *(const float4*)(W_p + h0);
    *(float4*)&wp[4] = *(const float4*)(W_p + h0 + 4);

    float hv[8], cv[8];
    float s = 0.f;
    #pragma unroll
    for (int k = 0; k < 8; k++) {
        float c  = sigf(gf[k]) * cc[k] + sigf(gi[k]) * tanhf(gg[k]);
        float hh = sigf(go[k]) * tanhf(c);
        cv[k] = c; hv[k] = hh;
        s += hh * wp[k];
    }
    *(float4*)(g_cx + hb + h0)     = *(float4*)&cv[0];
    *(float4*)(g_cx + hb + h0 + 4) = *(float4*)&cv[4];
    *(float4*)(g_hx + hb + h0)     = *(float4*)&hv[0];
    *(float4*)(g_hx + hb + h0 + 4) = *(float4*)&hv[4];

    // bf16x3 A-side write of new hx
    {
        __nv_bfloat16 hib[8], lob[8];
        #pragma unroll
        for (int k = 0; k < 8; k++) split_bf16(hv[k], hib[k], lob[k]);
        __nv_bfloat16* dst = g_hxb + (size_t)b * KB3 + h0;
        *(uint4*)(dst)        = *(uint4*)&hib[0];
        *(uint4*)(dst + 2048) = *(uint4*)&hib[0];
        *(uint4*)(dst + 4096) = *(uint4*)&lob[0];
    }

    #pragma unroll
    for (int o = 16; o; o >>= 1) s += __shfl_down_sync(0xffffffffu, s, o);
    if ((threadIdx.x & 31) == 0) red[threadIdx.x >> 5] = s;
    __syncthreads();
    if (threadIdx.x == 0) {
        float tot = 0.f;
        #pragma unroll
        for (int w = 0; w < 8; w++) tot += red[w];
        float gx   = sigf(tot + b_p[0]);
        float accn = g_gxacc[b] + gx;
        bool  halt = accn > 0.99f;              // 1.0 - EPS
        float rx   = halt ? (accn - 1.0f) : 0.f;
        float p    = gx - rx;
        g_gxacc[b] = accn - rx;
        s_p        = p;
        if (halt) g_halted[b] = 1;
    }
    __syncthreads();
    const float p = s_p;
    float* ahx = out + hb;
    float* acx = out + (size_t)BSZ * HID + hb;
    float av[8], xv[8];
    *(float4*)&av[0] = *(const float4*)(ahx + h0);
    *(float4*)&av[4] = *(const float4*)(ahx + h0 + 4);
    *(float4*)&xv[0] = *(const float4*)(acx + h0);
    *(float4*)&xv[4] = *(const float4*)(acx + h0 + 4);
    #pragma unroll
    for (int k = 0; k < 8; k++) {
        av[k] += p * hv[k];
        xv[k] += p * cv[k];
    }
    *(float4*)(ahx + h0)     = *(float4*)&av[0];
    *(float4*)(ahx + h0 + 4) = *(float4*)&av[4];
    *(float4*)(acx + h0)     = *(float4*)&xv[0];
    *(float4*)(acx + h0 + 4) = *(float4*)&xv[4];
}

// ---- compaction ----
__global__ void __launch_bounds__(1024)
k_compact(int t)
{
    if (t > g_done_step) return;
    __shared__ int s_count;
    if (threadIdx.x == 0) s_count = 0;
    __syncthreads();

    const int n = g_nactive;
    const int* cur = g_rowidx[t & 1];
    int* nxt = g_rowidx[(t + 1) & 1];

    #pragma unroll
    for (int u = 0; u < 2; u++) {
        int slot = threadIdx.x + u * 1024;
        if (slot < n) {
            int row = cur[slot];
            if (!g_halted[row]) {
                int pos = atomicAdd(&s_count, 1);
                nxt[pos] = row;
            }
        }
    }
    __syncthreads();
    int cnt = s_count;
    int pad_end = (cnt + 127) & ~127;
    for (int k = cnt + (int)threadIdx.x; k < pad_end; k += 1024) nxt[k] = 0;
    if (threadIdx.x == 0) {
        g_nactive = cnt;
        if (cnt == 0 && t < g_done_step) {
            g_done_step = t;
            g_ponder    = t + 1;
        }
    }
}

// ---------------- final: aout = ahx @ W_o.T + (sum p) * b_o ----------------
__global__ void __launch_bounds__(NTHR)
k_aout_mma(const float* __restrict__ b_o, float* __restrict__ out)
{
    __shared__ int rowmap[128];
    float acc[4][4][4] = {};
    int m0 = blockIdx.y * 128, n0 = blockIdx.x * 128;
    mma_gemm(g_ahxb, nullptr, g_wob, m0, n0, acc, rowmap);
    float* aout = out + (size_t)2 * BSZ * HID;
    int lane = threadIdx.x & 31, warpid = threadIdx.x >> 5;
    int wm = warpid >> 2, wn = warpid & 3;
    #pragma unroll
    for (int mi = 0; mi < 4; mi++)
        #pragma unroll
        for (int e2 = 0; e2 < 2; e2++) {
            int m = m0 + wm * 64 + mi * 16 + (lane >> 2) + e2 * 8;
            float sp = g_gxacc[m];
            #pragma unroll
            for (int ni = 0; ni < 4; ni++) {
                int n = n0 + wn * 32 + ni * 8 + (lane & 3) * 2;
                float2 w;
                w.x = acc[mi][ni][e2 * 2 + 0] + sp * b_o[n];
                w.y = acc[mi][ni][e2 * 2 + 1] + sp * b_o[n + 1];
                *(float2*)&aout[(size_t)m * OUTD + n] = w;
            }
        }
}

// ---------------- finalize ----------------
__global__ void k_fin(float* __restrict__ out, int out_size)
{
    if (blockIdx.x == 0 && threadIdx.x == 0)
        out[out_size - 1] = (float)g_ponder;
}

// ---------------- host ----------------
extern "C" void kernel_launch(void* const* d_in, const int* in_sizes, int n_in,
                              void* d_out, int out_size)
{
    const float* x    = (const float*)d_in[0];
    const float* hx0  = (const float*)d_in[1];
    const float* cx0  = (const float*)d_in[2];
    const float* W_ih = (const float*)d_in[3];
    const float* b_ih = (const float*)d_in[4];
    const float* W_hh = (const float*)d_in[5];
    const float* b_hh = (const float*)d_in[6];
    const float* W_p  = (const float*)d_in[7];
    const float* b_p  = (const float*)d_in[8];
    const float* W_o  = (const float*)d_in[9];
    const float* b_o  = (const float*)d_in[10];
    float* out = (float*)d_out;

    k_init<<<2048, NTHR>>>(hx0, cx0, out);
    k_pack<<<2048, NTHR>>>(x);
    k_cvtw<<<4096, NTHR>>>(W_ih, 0, G4);
    k_cvtw<<<4096, NTHR>>>(W_hh, 1, G4);
    k_cvtw<<<2048, NTHR>>>(W_o,  2, OUTD);

    dim3 gbig(G4 / 128, BSZ / 128);     // 64 x 16
    dim3 gout(OUTD / 128, BSZ / 128);   // 16 x 16
    k_base_mma<<<gbig, NTHR>>>(b_ih, b_hh);

    for (int t = 0; t < MAXP; t++) {
        k_gates_mma<<<gbig, NTHR>>>(W_ih, t);
        k_cellrow<<<BSZ, NTHR>>>(W_p, b_p, out, t);
        k_compact<<<1, 1024>>>(t);
    }
    k_cvt_ahx<<<2048, NTHR>>>(out);
    k_aout_mma<<<gout, NTHR>>>(b_o, out);
    k_fin<<<1, 1>>>(out, out_size);
}

// round 9
// speedup vs baseline: 4.7680x; 1.2278x over previous
#include <cuda_runtime.h>
#include <cuda_bf16.h>
#include <math.h>

#define BSZ   2048
#define HID   2048
#define G4    8192
#define OUTD  2048
#define INDIM 2047
#define KDIM  2048
#define KB3   6144          // 3 * KDIM (bf16x3 K-extension)
#define MAXP  100
#define NTHR  256
#define LDA   40            // smem row stride in elements (80B, 16B-aligned, conflict-free)
#define KCH   32
#define NCHUNK (KB3 / KCH)  // 192

// ---------------- device scratch ----------------
__device__ __align__(16) __nv_bfloat16 g_xpadb[(size_t)BSZ * KB3];  // A-side (hi,hi,lo)
__device__ __align__(16) __nv_bfloat16 g_hxb  [(size_t)BSZ * KB3];  // A-side
__device__ __align__(16) __nv_bfloat16 g_ahxb [(size_t)BSZ * KB3];  // A-side
__device__ __align__(16) __nv_bfloat16 g_wihb [(size_t)G4  * KB3];  // B-side (hi,lo,hi)
__device__ __align__(16) __nv_bfloat16 g_whhb [(size_t)G4  * KB3];  // B-side
__device__ __align__(16) __nv_bfloat16 g_wob  [(size_t)OUTD* KB3];  // B-side
__device__ __align__(16) float g_base [(size_t)BSZ * G4];
__device__ __align__(16) float g_gates[(size_t)BSZ * G4];
__device__ __align__(16) float g_hx   [(size_t)BSZ * HID];
__device__ __align__(16) float g_cx   [(size_t)BSZ * HID];
__device__ float g_gxacc[BSZ];
__device__ int   g_halted[BSZ];
__device__ int   g_rowidx[2][BSZ + 128];
__device__ int   g_blkdone[MAXP];
__device__ int   g_nactive;
__device__ int   g_done_step;
__device__ int   g_ponder;

__device__ __forceinline__ float sigf(float x) { return 1.0f / (1.0f + expf(-x)); }

__device__ __forceinline__ void split_bf16(float v, __nv_bfloat16& hi, __nv_bfloat16& lo)
{
    hi = __float2bfloat16(v);
    lo = __float2bfloat16(v - __bfloat162float(hi));
}

// ---------------- PTX helpers ----------------
__device__ __forceinline__ unsigned su32(const void* p)
{
    return (unsigned)__cvta_generic_to_shared(p);
}
__device__ __forceinline__ void cp16(unsigned dst, const void* src)
{
    asm volatile("cp.async.cg.shared.global [%0], [%1], 16;" :: "r"(dst), "l"(src));
}
__device__ __forceinline__ void cp_commit()
{
    asm volatile("cp.async.commit_group;" ::: "memory");
}
template <int N> __device__ __forceinline__ void cp_wait()
{
    asm volatile("cp.async.wait_group %0;" :: "n"(N) : "memory");
}
__device__ __forceinline__ void ldsm4(unsigned& r0, unsigned& r1, unsigned& r2, unsigned& r3,
                                      unsigned addr)
{
    asm volatile("ldmatrix.sync.aligned.m8n8.x4.shared.b16 {%0,%1,%2,%3}, [%4];"
                 : "=r"(r0), "=r"(r1), "=r"(r2), "=r"(r3) : "r"(addr));
}
__device__ __forceinline__ void mma16816(float& d0, float& d1, float& d2, float& d3,
                                         unsigned a0, unsigned a1, unsigned a2, unsigned a3,
                                         unsigned b0, unsigned b1)
{
    asm volatile("mma.sync.aligned.m16n8k16.row.col.f32.bf16.bf16.f32 "
                 "{%0,%1,%2,%3}, {%4,%5,%6,%7}, {%8,%9}, {%0,%1,%2,%3};"
                 : "+f"(d0), "+f"(d1), "+f"(d2), "+f"(d3)
                 : "r"(a0), "r"(a1), "r"(a2), "r"(a3), "r"(b0), "r"(b1));
}

// ------------- 128x128 bf16 MMA GEMM tile: acc += A'(MxK') @ B'(NxK')^T -------------
// 256 threads = 8 warps (2x4). Warp tile 64x32. cp.async double-buffered smem,
// ldmatrix fragment loads (mapping derived from PTX mma fragment tables).
__device__ __forceinline__ void mma_gemm(
    const __nv_bfloat16* __restrict__ A, const int* __restrict__ rows,
    const __nv_bfloat16* __restrict__ B,
    int m0, int n0, float (&acc)[4][4][4], int* rowmap)
{
    __shared__ __align__(16) __nv_bfloat16 As[2][128 * LDA];
    __shared__ __align__(16) __nv_bfloat16 Bs[2][128 * LDA];
    const int tid = threadIdx.x;

    if (rows) {
        if (tid < 128) rowmap[tid] = rows[m0 + tid];
        __syncthreads();
    }

    // per-thread cp.async assignment: 2 x 16B for A, 2 x 16B for B per chunk
    const unsigned suA[2] = { su32(&As[0][0]), su32(&As[1][0]) };
    const unsigned suB[2] = { su32(&Bs[0][0]), su32(&Bs[1][0]) };
    const __nv_bfloat16* srcA[2];
    const __nv_bfloat16* srcB[2];
    unsigned offA[2], offB[2];
    #pragma unroll
    for (int u = 0; u < 2; u++) {
        int idx = tid * 2 + u;          // 0..511
        int row = idx >> 2, sub = idx & 3;
        int ar  = rows ? rowmap[row] : (m0 + row);
        srcA[u] = A + (size_t)ar * KB3 + sub * 8;
        srcB[u] = B + (size_t)(n0 + row) * KB3 + sub * 8;
        offA[u] = (unsigned)(row * (LDA * 2) + sub * 16);   // bytes
        offB[u] = offA[u];
    }

    const int lane = tid & 31, warpid = tid >> 5;
    const int wm = warpid >> 2, wn = warpid & 3;
    // A ldsm4 lane mapping: lanes 0-7 rows 0-7 @k, 8-15 rows 8-15 @k,
    //                       16-23 rows 0-7 @k+8, 24-31 rows 8-15 @k+8
    const int a_r = lane & 15;
    const int a_c = (lane >> 4) << 3;
    // B ldsm4 lane mapping: 0-7 rows 0-7 @k, 8-15 rows 0-7 @k+8,
    //                       16-23 rows 8-15 @k, 24-31 rows 8-15 @k+8
    const int b_r = ((lane >> 4) << 3) + (lane & 7);
    const int b_c = ((lane >> 3) & 1) << 3;

    // prologue: chunk 0 into buf 0
    #pragma unroll
    for (int u = 0; u < 2; u++) cp16(suA[0] + offA[u], srcA[u]);
    #pragma unroll
    for (int u = 0; u < 2; u++) cp16(suB[0] + offB[u], srcB[u]);
    cp_commit();

    for (int ch = 0; ch < NCHUNK; ch++) {
        const int buf = ch & 1;
        if (ch + 1 < NCHUNK) {
            const int kb2 = (ch + 1) * KCH;
            const int nb = buf ^ 1;
            #pragma unroll
            for (int u = 0; u < 2; u++) cp16(suA[nb] + offA[u], srcA[u] + kb2);
            #pragma unroll
            for (int u = 0; u < 2; u++) cp16(suB[nb] + offB[u], srcB[u] + kb2);
            cp_commit();
            cp_wait<1>();
        } else {
            cp_wait<0>();
        }
        __syncthreads();

        #pragma unroll
        for (int kh = 0; kh < 2; kh++) {
            const int kb = kh * 16;
            unsigned af[4][4], bq[2][4];
            #pragma unroll
            for (int mi = 0; mi < 4; mi++) {
                int r = wm * 64 + mi * 16 + a_r;
                ldsm4(af[mi][0], af[mi][1], af[mi][2], af[mi][3],
                      suA[buf] + (unsigned)(r * (LDA * 2) + (kb + a_c) * 2));
            }
            #pragma unroll
            for (int np = 0; np < 2; np++) {
                int r = wn * 32 + np * 16 + b_r;
                ldsm4(bq[np][0], bq[np][1], bq[np][2], bq[np][3],
                      suB[buf] + (unsigned)(r * (LDA * 2) + (kb + b_c) * 2));
            }
            #pragma unroll
            for (int mi = 0; mi < 4; mi++) {
                #pragma unroll
                for (int np = 0; np < 2; np++) {
                    mma16816(acc[mi][np*2][0], acc[mi][np*2][1], acc[mi][np*2][2], acc[mi][np*2][3],
                             af[mi][0], af[mi][1], af[mi][2], af[mi][3],
                             bq[np][0], bq[np][1]);
                    mma16816(acc[mi][np*2+1][0], acc[mi][np*2+1][1], acc[mi][np*2+1][2], acc[mi][np*2+1][3],
                             af[mi][0], af[mi][1], af[mi][2], af[mi][3],
                             bq[np][2], bq[np][3]);
                }
            }
        }
        __syncthreads();
    }
}

// ---------------- init ----------------
__global__ void __launch_bounds__(NTHR)
k_init(const float* __restrict__ hx0, const float* __restrict__ cx0,
       float* __restrict__ out)
{
    size_t i      = (size_t)blockIdx.x * blockDim.x + threadIdx.x;
    size_t stride = (size_t)gridDim.x * blockDim.x;
    for (size_t k = i; k < (size_t)2 * BSZ * HID; k += stride) out[k] = 0.f;
    for (size_t k = i; k < (size_t)BSZ * HID; k += stride) {
        float h = hx0[k], c = cx0[k];
        g_hx[k] = h;
        g_cx[k] = c;
        size_t row = k >> 11, col = k & 2047;
        __nv_bfloat16 hi, lo;
        split_bf16(h, hi, lo);
        g_hxb[row * KB3 + col]        = hi;
        g_hxb[row * KB3 + 2048 + col] = hi;
        g_hxb[row * KB3 + 4096 + col] = lo;
    }
    for (size_t k = i; k < BSZ + 128; k += stride) {
        if (k < BSZ) {
            g_gxacc[k]  = 0.f;
            g_halted[k] = 0;
            g_rowidx[0][k] = (int)k;
        } else {
            g_rowidx[0][k] = 0;
        }
    }
    for (size_t k = i; k < MAXP; k += stride) g_blkdone[k] = 0;
    if (i == 0) {
        g_nactive   = BSZ;
        g_done_step = (1 << 30);
        g_ponder    = MAXP;
    }
}

// ---------------- pack x into bf16x3 A-layout ----------------
__global__ void __launch_bounds__(NTHR)
k_pack(const float* __restrict__ x)
{
    size_t i      = (size_t)blockIdx.x * blockDim.x + threadIdx.x;
    size_t stride = (size_t)gridDim.x * blockDim.x;
    for (size_t k = i; k < (size_t)BSZ * KDIM; k += stride) {
        size_t row = k >> 11, col = k & 2047;
        float v = (col < INDIM) ? x[row * INDIM + col] : 0.f;
        __nv_bfloat16 hi, lo;
        split_bf16(v, hi, lo);
        g_xpadb[row * KB3 + col]        = hi;
        g_xpadb[row * KB3 + 2048 + col] = hi;
        g_xpadb[row * KB3 + 4096 + col] = lo;
    }
}

// -------- weight conversion to bf16x3 B-layout (hi,lo,hi) --------
// Destination selected by tag inside device code (host-shadow-symbol trap).
__global__ void __launch_bounds__(NTHR)
k_cvtw(const float* __restrict__ W, int which, int nrows)
{
    __nv_bfloat16* Wb = (which == 0) ? g_wihb : (which == 1) ? g_whhb : g_wob;
    size_t total  = (size_t)nrows * KDIM;
    size_t i      = (size_t)blockIdx.x * blockDim.x + threadIdx.x;
    size_t stride = (size_t)gridDim.x * blockDim.x;
    for (size_t k = i; k < total; k += stride) {
        size_t row = k >> 11, col = k & 2047;
        __nv_bfloat16 hi, lo;
        split_bf16(W[k], hi, lo);
        Wb[row * KB3 + col]        = hi;
        Wb[row * KB3 + 2048 + col] = lo;
        Wb[row * KB3 + 4096 + col] = hi;
    }
}

// ---------------- ahx -> bf16x3 A-layout ----------------
__global__ void __launch_bounds__(NTHR)
k_cvt_ahx(const float* __restrict__ out)
{
    size_t i      = (size_t)blockIdx.x * blockDim.x + threadIdx.x;
    size_t stride = (size_t)gridDim.x * blockDim.x;
    for (size_t k = i; k < (size_t)BSZ * HID; k += stride) {
        size_t row = k >> 11, col = k & 2047;
        __nv_bfloat16 hi, lo;
        split_bf16(out[k], hi, lo);
        g_ahxb[row * KB3 + col]        = hi;
        g_ahxb[row * KB3 + 2048 + col] = hi;
        g_ahxb[row * KB3 + 4096 + col] = lo;
    }
}

// ---------------- base = xpad @ W_ih.T + b_ih + b_hh ----------------
__global__ void __launch_bounds__(NTHR)
k_base_mma(const float* __restrict__ b_ih, const float* __restrict__ b_hh)
{
    __shared__ int rowmap[128];
    float acc[4][4][4] = {};
    int m0 = blockIdx.y * 128, n0 = blockIdx.x * 128;
    mma_gemm(g_xpadb, nullptr, g_wihb, m0, n0, acc, rowmap);
    int lane = threadIdx.x & 31, warpid = threadIdx.x >> 5;
    int wm = warpid >> 2, wn = warpid & 3;
    #pragma unroll
    for (int mi = 0; mi < 4; mi++)
        #pragma unroll
        for (int e2 = 0; e2 < 2; e2++) {
            int m = m0 + wm * 64 + mi * 16 + (lane >> 2) + e2 * 8;
            #pragma unroll
            for (int ni = 0; ni < 4; ni++) {
                int n = n0 + wn * 32 + ni * 8 + (lane & 3) * 2;
                float2 w;
                w.x = acc[mi][ni][e2 * 2 + 0] + b_ih[n]     + b_hh[n];
                w.y = acc[mi][ni][e2 * 2 + 1] + b_ih[n + 1] + b_hh[n + 1];
                *(float2*)&g_base[(size_t)m * G4 + n] = w;
            }
        }
}

// ---- gates[slot] = base[row] + hx[row] @ W_hh.T (+ flag col at t==0) ----
__global__ void __launch_bounds__(NTHR)
k_gates_mma(const float* __restrict__ W_ih, int t)
{
    if (t > g_done_step) return;
    int m0 = blockIdx.y * 128;
    if (m0 >= g_nactive) return;
    int n0 = blockIdx.x * 128;
    __shared__ int rowmap[128];
    float acc[4][4][4] = {};
    mma_gemm(g_hxb, g_rowidx[t & 1], g_whhb, m0, n0, acc, rowmap);

    int lane = threadIdx.x & 31, warpid = threadIdx.x >> 5;
    int wm = warpid >> 2, wn = warpid & 3;
    #pragma unroll
    for (int mi = 0; mi < 4; mi++)
        #pragma unroll
        for (int e2 = 0; e2 < 2; e2++) {
            int ml   = wm * 64 + mi * 16 + (lane >> 2) + e2 * 8;
            int slot = m0 + ml;
            int row  = rowmap[ml];
            #pragma unroll
            for (int ni = 0; ni < 4; ni++) {
                int n = n0 + wn * 32 + ni * 8 + (lane & 3) * 2;
                float v0 = acc[mi][ni][e2 * 2 + 0] + g_base[(size_t)row * G4 + n];
                float v1 = acc[mi][ni][e2 * 2 + 1] + g_base[(size_t)row * G4 + n + 1];
                if (t == 0) {
                    v0 += W_ih[(size_t)n       * KDIM + INDIM];
                    v1 += W_ih[(size_t)(n + 1) * KDIM + INDIM];
                }
                float2 w; w.x = v0; w.y = v1;
                *(float2*)&g_gates[(size_t)slot * G4 + n] = w;
            }
        }
}

// ---- fused: LSTM cell + ponder + ahx/acx accumulation + compaction ----
__global__ void __launch_bounds__(NTHR)
k_cellrow(const float* __restrict__ W_p, const float* __restrict__ b_p,
          float* __restrict__ out, int t)
{
    if (t > g_done_step) return;
    const int slot = blockIdx.x;
    const int nact = g_nactive;

    if (slot < nact) {
        const int b = g_rowidx[t & 1][slot];
        __shared__ float red[8];
        __shared__ float s_p;

        const size_t gb = (size_t)slot * G4;
        const size_t hb = (size_t)b * HID;
        const int h0 = threadIdx.x * 8;

        float gi[8], gf[8], gg[8], go[8], cc[8], wp[8];
        *(float4*)&gi[0] = *(const float4*)(g_gates + gb + h0);
        *(float4*)&gi[4] = *(const float4*)(g_gates + gb + h0 + 4);
        *(float4*)&gf[0] = *(const float4*)(g_gates + gb + HID + h0);
        *(float4*)&gf[4] = *(const float4*)(g_gates + gb + HID + h0 + 4);
        *(float4*)&gg[0] = *(const float4*)(g_gates + gb + 2*HID + h0);
        *(float4*)&gg[4] = *(const float4*)(g_gates + gb + 2*HID + h0 + 4);
        *(float4*)&go[0] = *(const float4*)(g_gates + gb + 3*HID + h0);
        *(float4*)&go[4] = *(const float4*)(g_gates + gb + 3*HID + h0 + 4);
        *(float4*)&cc[0] = *(const float4*)(g_cx + hb + h0);
        *(float4*)&cc[4] = *(const float4*)(g_cx + hb + h0 + 4);
        *(float4*)&wp[0] = *(const float4*)(W_p + h0);
        *(float4*)&wp[4] = *(const float4*)(W_p + h0 + 4);

        float hv[8], cv[8];
        float s = 0.f;
        #pragma unroll
        for (int k = 0; k < 8; k++) {
            float c  = sigf(gf[k]) * cc[k] + sigf(gi[k]) * tanhf(gg[k]);
            float hh = sigf(go[k]) * tanhf(c);
            cv[k] = c; hv[k] = hh;
            s += hh * wp[k];
        }
        *(float4*)(g_cx + hb + h0)     = *(float4*)&cv[0];
        *(float4*)(g_cx + hb + h0 + 4) = *(float4*)&cv[4];
        *(float4*)(g_hx + hb + h0)     = *(float4*)&hv[0];
        *(float4*)(g_hx + hb + h0 + 4) = *(float4*)&hv[4];

        {
            __nv_bfloat16 hib[8], lob[8];
            #pragma unroll
            for (int k = 0; k < 8; k++) split_bf16(hv[k], hib[k], lob[k]);
            __nv_bfloat16* dst = g_hxb + (size_t)b * KB3 + h0;
            *(uint4*)(dst)        = *(uint4*)&hib[0];
            *(uint4*)(dst + 2048) = *(uint4*)&hib[0];
            *(uint4*)(dst + 4096) = *(uint4*)&lob[0];
        }

        #pragma unroll
        for (int o = 16; o; o >>= 1) s += __shfl_down_sync(0xffffffffu, s, o);
        if ((threadIdx.x & 31) == 0) red[threadIdx.x >> 5] = s;
        __syncthreads();
        if (threadIdx.x == 0) {
            float tot = 0.f;
            #pragma unroll
            for (int w = 0; w < 8; w++) tot += red[w];
            float gx   = sigf(tot + b_p[0]);
            float accn = g_gxacc[b] + gx;
            bool  halt = accn > 0.99f;          // 1.0 - EPS
            float rx   = halt ? (accn - 1.0f) : 0.f;
            float p    = gx - rx;
            g_gxacc[b] = accn - rx;
            s_p        = p;
            if (halt) g_halted[b] = 1;
        }
        __syncthreads();
        const float p = s_p;
        float* ahx = out + hb;
        float* acx = out + (size_t)BSZ * HID + hb;
        float av[8], xv[8];
        *(float4*)&av[0] = *(const float4*)(ahx + h0);
        *(float4*)&av[4] = *(const float4*)(ahx + h0 + 4);
        *(float4*)&xv[0] = *(const float4*)(acx + h0);
        *(float4*)&xv[4] = *(const float4*)(acx + h0 + 4);
        #pragma unroll
        for (int k = 0; k < 8; k++) {
            av[k] += p * hv[k];
            xv[k] += p * cv[k];
        }
        *(float4*)(ahx + h0)     = *(float4*)&av[0];
        *(float4*)(ahx + h0 + 4) = *(float4*)&av[4];
        *(float4*)(acx + h0)     = *(float4*)&xv[0];
        *(float4*)(acx + h0 + 4) = *(float4*)&xv[4];
    }

    // ---- last-arriving block performs compaction for step t ----
    __shared__ int s_old;
    __threadfence();
    __syncthreads();
    if (threadIdx.x == 0) s_old = atomicAdd(&g_blkdone[t], 1);
    __syncthreads();
    if (s_old == BSZ - 1) {
        __shared__ int s_cnt;
        if (threadIdx.x == 0) s_cnt = 0;
        __syncthreads();
        const int* cur = g_rowidx[t & 1];
        int* nxt = g_rowidx[(t + 1) & 1];
        for (int s2 = threadIdx.x; s2 < nact; s2 += NTHR) {
            int row = cur[s2];
            if (!g_halted[row]) nxt[atomicAdd(&s_cnt, 1)] = row;
        }
        __syncthreads();
        int cnt = s_cnt;
        int pad_end = (cnt + 127) & ~127;
        for (int k2 = cnt + (int)threadIdx.x; k2 < pad_end; k2 += NTHR) nxt[k2] = 0;
        if (threadIdx.x == 0) {
            g_nactive = cnt;
            if (cnt == 0) {
                g_done_step = t;
                g_ponder    = t + 1;
            }
            __threadfence();
        }
    }
}

// ---------------- final: aout = ahx @ W_o.T + (sum p) * b_o ----------------
__global__ void __launch_bounds__(NTHR)
k_aout_mma(const float* __restrict__ b_o, float* __restrict__ out)
{
    __shared__ int rowmap[128];
    float acc[4][4][4] = {};
    int m0 = blockIdx.y * 128, n0 = blockIdx.x * 128;
    mma_gemm(g_ahxb, nullptr, g_wob, m0, n0, acc, rowmap);
    float* aout = out + (size_t)2 * BSZ * HID;
    int lane = threadIdx.x & 31, warpid = threadIdx.x >> 5;
    int wm = warpid >> 2, wn = warpid & 3;
    #pragma unroll
    for (int mi = 0; mi < 4; mi++)
        #pragma unroll
        for (int e2 = 0; e2 < 2; e2++) {
            int m = m0 + wm * 64 + mi * 16 + (lane >> 2) + e2 * 8;
            float sp = g_gxacc[m];
            #pragma unroll
            for (int ni = 0; ni < 4; ni++) {
                int n = n0 + wn * 32 + ni * 8 + (lane & 3) * 2;
                float2 w;
                w.x = acc[mi][ni][e2 * 2 + 0] + sp * b_o[n];
                w.y = acc[mi][ni][e2 * 2 + 1] + sp * b_o[n + 1];
                *(float2*)&aout[(size_t)m * OUTD + n] = w;
            }
        }
}

// ---------------- finalize ----------------
__global__ void k_fin(float* __restrict__ out, int out_size)
{
    if (blockIdx.x == 0 && threadIdx.x == 0)
        out[out_size - 1] = (float)g_ponder;
}

// ---------------- host ----------------
extern "C" void kernel_launch(void* const* d_in, const int* in_sizes, int n_in,
                              void* d_out, int out_size)
{
    const float* x    = (const float*)d_in[0];
    const float* hx0  = (const float*)d_in[1];
    const float* cx0  = (const float*)d_in[2];
    const float* W_ih = (const float*)d_in[3];
    const float* b_ih = (const float*)d_in[4];
    const float* W_hh = (const float*)d_in[5];
    const float* b_hh = (const float*)d_in[6];
    const float* W_p  = (const float*)d_in[7];
    const float* b_p  = (const float*)d_in[8];
    const float* W_o  = (const float*)d_in[9];
    const float* b_o  = (const float*)d_in[10];
    float* out = (float*)d_out;

    k_init<<<2048, NTHR>>>(hx0, cx0, out);
    k_pack<<<2048, NTHR>>>(x);
    k_cvtw<<<4096, NTHR>>>(W_ih, 0, G4);
    k_cvtw<<<4096, NTHR>>>(W_hh, 1, G4);
    k_cvtw<<<2048, NTHR>>>(W_o,  2, OUTD);

    dim3 gbig(G4 / 128, BSZ / 128);     // 64 x 16
    dim3 gout(OUTD / 128, BSZ / 128);   // 16 x 16
    k_base_mma<<<gbig, NTHR>>>(b_ih, b_hh);

    for (int t = 0; t < MAXP; t++) {
        k_gates_mma<<<gbig, NTHR>>>(W_ih, t);
        k_cellrow<<<BSZ, NTHR>>>(W_p, b_p, out, t);
    }
    k_cvt_ahx<<<2048, NTHR>>>(out);
    k_aout_mma<<<gout, NTHR>>>(b_o, out);
    k_fin<<<1, 1>>>(out, out_size);
}